// round 8
// baseline (speedup 1.0000x reference)
#include <cuda_runtime.h>

// Fused PreNorm cross-attention (query-length-1 over m=16 neighbors), fp32.
// Persistent-CTA design: Wq+Wkv live in SMEM (loaded once), Wo lives in
// registers; grid-stride loop over the 65536 (b,n) points. Hot kv GEMM uses
// packed fma.rn.f32x2 (sm_103a FFMA2) for 2 MACs/lane/instr.

#define THREADS 256
#define DIMX 128
#define MROWS 16
#define YSTR 20   // transposed-yn row stride (floats), float4-aligned, odd/32 enough

// ---- smem layout (float indices) ----
#define OFF_WQ   0        // 16384  : Wq [128][128]
#define OFF_WKV  16384    // 32768  : Wkv [128][256]
#define OFF_KV   49152    // 4096   : kv result [16][256]; ALSO raw staging (2176 f)
#define OFF_YT   53248    // 2560   : yn transposed [128][YSTR]
#define OFF_XN   55808    // 128
#define OFF_XO   55936    // 128
#define OFF_Q    56064    // 128
#define OFF_AO   56192    // 128
#define OFF_AT   56320    // 64
#define OFF_BUF  56384    // 128
#define OFF_BO   56512    // 128
#define OFF_G    56640    // 128
#define OFF_B    56768    // 128
#define SMEM_FLOATS 56896 // 227584 bytes

__device__ __forceinline__ unsigned long long pk2(float v) {
    unsigned long long r;
    unsigned int b = __float_as_uint(v);
    asm("mov.b64 %0, {%1, %1};" : "=l"(r) : "r"(b));
    return r;
}
__device__ __forceinline__ void ffma2(unsigned long long& a,
                                      unsigned long long xv,
                                      unsigned long long wv) {
    asm("fma.rn.f32x2 %0, %1, %2, %0;" : "+l"(a) : "l"(xv), "l"(wv));
}
__device__ __forceinline__ float2 upk2(unsigned long long v) {
    unsigned int lo, hi;
    asm("mov.b64 {%0, %1}, %2;" : "=r"(lo), "=r"(hi) : "l"(v));
    return make_float2(__uint_as_float(lo), __uint_as_float(hi));
}

__global__ void __launch_bounds__(THREADS, 1)
ca_fused_kernel(const float* __restrict__ x,
                const float* __restrict__ y,
                const float* __restrict__ ln_g,
                const float* __restrict__ ln_b,
                const float* __restrict__ Wq,
                const float* __restrict__ Wkv,
                const float* __restrict__ Wo,
                const float* __restrict__ bo,
                float* __restrict__ out,
                int P)
{
    extern __shared__ float sm[];
    float* sWq  = sm + OFF_WQ;
    float* sWkv = sm + OFF_WKV;
    float* sKV  = sm + OFF_KV;
    float* sYT  = sm + OFF_YT;
    float* sXN  = sm + OFF_XN;
    float* sXO  = sm + OFF_XO;
    float* sQ   = sm + OFF_Q;
    float* sAO  = sm + OFF_AO;
    float* sAT  = sm + OFF_AT;
    float* sBUF = sm + OFF_BUF;
    float* sBO  = sm + OFF_BO;
    float* sG   = sm + OFF_G;
    float* sB   = sm + OFF_B;

    const int tid  = threadIdx.x;
    const int warp = tid >> 5;
    const int lane = tid & 31;
    const int rg   = tid >> 6;   // 0..3 : row group (4 rows of kv)
    const int cg   = tid & 63;   // 0..63: col group (4 cols of kv)
    const int jj   = tid & 127;  // output column for Wo GEMM
    const int hf   = tid >> 7;   // 0/1  : i-half for Wo GEMM

    // ---- load weights into SMEM (once) ----
    {
        const float4* s4 = (const float4*)Wq;
        float4* d4 = (float4*)sWq;
        for (int u = tid; u < 4096; u += THREADS) d4[u] = s4[u];
        const float4* s42 = (const float4*)Wkv;
        float4* d42 = (float4*)sWkv;
        for (int u = tid; u < 8192; u += THREADS) d42[u] = s42[u];
        if (tid < 128) { sBO[tid] = bo[tid]; sG[tid] = ln_g[tid]; sB[tid] = ln_b[tid]; }
    }
    // ---- Wo into registers: thread holds Wo[hf*64 + ii][jj], ii=0..63 ----
    float wo[64];
#pragma unroll
    for (int ii = 0; ii < 64; ++ii) wo[ii] = Wo[(hf * 64 + ii) * 128 + jj];

    __syncthreads();

    for (int pt = blockIdx.x; pt < P; pt += gridDim.x) {
        // ---- stage raw y (16x128) + x (128) into sKV region (coalesced f4) ----
        {
            const float4* y4 = (const float4*)y + (size_t)pt * 512;
            const float4* x4 = (const float4*)x + (size_t)pt * 32;
            float4* raw = (float4*)sKV;
            for (int u = tid; u < 544; u += THREADS)
                raw[u] = (u < 512) ? y4[u] : x4[u - 512];
        }
        __syncthreads();

        // ---- LayerNorm: 17 rows (16 y rows -> sYT transposed, row 16 = x -> sXN) ----
        for (int r = warp; r < 17; r += 8) {
            const float* row = sKV + r * 128;
            float v0 = row[lane], v1 = row[lane + 32], v2 = row[lane + 64], v3 = row[lane + 96];
            float s  = v0 + v1 + v2 + v3;
            float q2 = v0 * v0 + v1 * v1 + v2 * v2 + v3 * v3;
#pragma unroll
            for (int o = 16; o > 0; o >>= 1) {
                s  += __shfl_xor_sync(0xffffffffu, s,  o);
                q2 += __shfl_xor_sync(0xffffffffu, q2, o);
            }
            float mu  = s * (1.0f / 128.0f);
            float var = q2 * (1.0f / 128.0f) - mu * mu;
            float rs  = rsqrtf(var + 1e-5f);
            float vs[4] = {v0, v1, v2, v3};
            if (r < 16) {
#pragma unroll
                for (int k = 0; k < 4; ++k) {
                    int i = lane + k * 32;
                    sYT[i * YSTR + r] = (vs[k] - mu) * rs * sG[i] + sB[i];
                }
            } else {
#pragma unroll
                for (int k = 0; k < 4; ++k) {
                    int i = lane + k * 32;
                    sXN[i] = (vs[k] - mu) * rs * sG[i] + sB[i];
                    sXO[i] = vs[k];
                }
            }
        }
        __syncthreads();

        // ---- kv GEMM: yn[16,128] @ Wkv[128,256] -> sKV[16,256]  (packed f32x2) ----
        unsigned long long a00 = 0, a01 = 0, a10 = 0, a11 = 0;
        unsigned long long a20 = 0, a21 = 0, a30 = 0, a31 = 0;
        {
            const float* yt = sYT + rg * 4;
            const float* wk = sWkv + cg * 4;
#pragma unroll 4
            for (int i = 0; i < 128; ++i) {
                float4 yv = *(const float4*)(yt + i * YSTR);         // 4 rows, broadcast
                ulonglong2 wv = *(const ulonglong2*)(wk + i * 256);  // 4 cols as 2x f32x2
                unsigned long long p;
                p = pk2(yv.x); ffma2(a00, p, wv.x); ffma2(a01, p, wv.y);
                p = pk2(yv.y); ffma2(a10, p, wv.x); ffma2(a11, p, wv.y);
                p = pk2(yv.z); ffma2(a20, p, wv.x); ffma2(a21, p, wv.y);
                p = pk2(yv.w); ffma2(a30, p, wv.x); ffma2(a31, p, wv.y);
            }
        }
        {
            float* dst = sKV + (rg * 4) * 256 + cg * 4;
            float2 lo, hi;
            lo = upk2(a00); hi = upk2(a01); *(float4*)(dst)        = make_float4(lo.x, lo.y, hi.x, hi.y);
            lo = upk2(a10); hi = upk2(a11); *(float4*)(dst + 256)  = make_float4(lo.x, lo.y, hi.x, hi.y);
            lo = upk2(a20); hi = upk2(a21); *(float4*)(dst + 512)  = make_float4(lo.x, lo.y, hi.x, hi.y);
            lo = upk2(a30); hi = upk2(a31); *(float4*)(dst + 768)  = make_float4(lo.x, lo.y, hi.x, hi.y);
        }

        // ---- q GEMM: xn[128] @ Wq[128,128] ----
        if (tid < 128) {
            float a = 0.0f;
#pragma unroll 8
            for (int i = 0; i < 128; ++i) a = fmaf(sXN[i], sWq[i * 128 + tid], a);
            sQ[tid] = a;
        }
        __syncthreads();

        // ---- dots + softmax over m=16, per head (threads 0..63) ----
        if (tid < 64) {
            int h = tid >> 4, m = tid & 15;
            const float* kk = sKV + m * 256 + h * 32;  // k = cols [0,128)
            const float* qq = sQ + h * 32;
            float dsum = 0.0f;
#pragma unroll
            for (int dd = 0; dd < 8; ++dd) {
                float4 k4 = *(const float4*)(kk + dd * 4);
                float4 q4 = *(const float4*)(qq + dd * 4);
                dsum += k4.x * q4.x + k4.y * q4.y + k4.z * q4.z + k4.w * q4.w;
            }
            dsum *= 0.17677669529663687f;  // 32^-0.5
            float mx = dsum;
#pragma unroll
            for (int o = 8; o > 0; o >>= 1)
                mx = fmaxf(mx, __shfl_xor_sync(0xffffffffu, mx, o));
            float e = __expf(dsum - mx);
            float se = e;
#pragma unroll
            for (int o = 8; o > 0; o >>= 1)
                se += __shfl_xor_sync(0xffffffffu, se, o);
            sAT[tid] = e / se;
        }
        __syncthreads();

        // ---- attention output: ao[h,d] = sum_m attn[h,m] * v[m,h,d] ----
        if (tid < 128) {
            int h = tid >> 5, d = tid & 31;
            const float* vv = sKV + 128 + h * 32 + d;  // v = cols [128,256)
            const float* at = sAT + h * 16;
            float a = 0.0f;
#pragma unroll
            for (int m = 0; m < 16; ++m) a = fmaf(at[m], vv[m * 256], a);
            sAO[tid] = a;
        }
        __syncthreads();

        // ---- out GEMM: ao[128] @ Wo[128,128] + bo + x  (Wo in registers) ----
        {
            const float* ain = sAO + hf * 64;
            float p = 0.0f;
#pragma unroll
            for (int ii = 0; ii < 64; ++ii) p = fmaf(ain[ii], wo[ii], p);
            if (hf) sBUF[jj] = p;
            __syncthreads();
            if (!hf) out[(size_t)pt * 128 + jj] = p + sBUF[jj] + sBO[jj] + sXO[jj];
        }
        __syncthreads();  // protect sKV/sBUF before next point's staging
    }
}

extern "C" void kernel_launch(void* const* d_in, const int* in_sizes, int n_in,
                              void* d_out, int out_size) {
    const float* x    = (const float*)d_in[0];
    const float* y    = (const float*)d_in[1];
    const float* ln_g = (const float*)d_in[2];
    const float* ln_b = (const float*)d_in[3];
    const float* Wq   = (const float*)d_in[4];
    const float* Wkv  = (const float*)d_in[5];
    const float* Wo   = (const float*)d_in[6];
    const float* bo   = (const float*)d_in[7];
    float* out = (float*)d_out;

    const int P = in_sizes[0] / 128;  // total (b*n) points

    int dev = 0;
    cudaGetDevice(&dev);
    int sms = 0;
    cudaDeviceGetAttribute(&sms, cudaDevAttrMultiProcessorCount, dev);
    if (sms <= 0) sms = 148;

    const size_t smem_bytes = (size_t)SMEM_FLOATS * sizeof(float);  // 227584
    cudaFuncSetAttribute(ca_fused_kernel,
                         cudaFuncAttributeMaxDynamicSharedMemorySize,
                         (int)smem_bytes);

    ca_fused_kernel<<<sms, THREADS, smem_bytes>>>(
        x, y, ln_g, ln_b, Wq, Wkv, Wo, bo, out, P);
}